// round 17
// baseline (speedup 1.0000x reference)
#include <cuda_runtime.h>

// ---------------------------------------------------------------------------
// PhotonicLayer via TF32 tensor cores (mma.sync.m16n8k8), fragment-packed.
// Real GEMM: X=[xr|xi] (Bx128), W=[[Ur,-Ui],[Ui,Ur]] (128x128), out'=X@W^T.
// K1: build U — one thread per column, per-thread LOCAL ping-pong buffers
//     (exact no-alias -> pipelined loads), zero barriers in the scan,
//     identity-row synthesis (no copies). Emits W in B-fragment order.
// K2: tensor-core GEMM (R16): fragment-packed A in smem, fully unrolled
//     mainloop, register epilogue with in-warp re/im pairing.
// ---------------------------------------------------------------------------

#define SIZE 64
#define NPH 2016
#define LOSS_AMP 0.9942600740f      // 10^(-0.05/20)
#define KERR 2.6e-17f               // NONLINEAR_COEFF * 1000

// W in fragment order: flat idx = (((n8t*16 + ks)*32 + lane)*2 + q)
__device__ unsigned g_Wfrag[16 * 16 * 32 * 2];   // 64 KB

// ---------------------------- build kernel --------------------------------
__device__ __forceinline__ void w_store(int np, int kp, float v) {
    unsigned tv;
    asm("cvt.rna.tf32.f32 %0, %1;" : "=r"(tv) : "f"(v));
    const int n8t = np >> 3, g = np & 7;
    const int ks = kp >> 3, t4 = kp & 3, q = (kp >> 2) & 1;
    g_Wfrag[(((n8t * 16 + ks) * 32 + g * 4 + t4) << 1) + q] = tv;
}

// One Reck layer over a thread-private column: read src, write dst.
// Rows >= i of src are stale; row i of the true state is still identity.
__device__ __forceinline__ void layer_col(
    int i, int kbase, const float2 (&src)[SIZE], float2 (&dst)[SIZE],
    const float2* __restrict__ ang, int t)
{
    float ar = src[0].x, ai = src[0].y;
    #pragma unroll 8
    for (int j = 0; j < i - 1; ++j) {
        const float2 a2 = ang[kbase + j];        // static shared, uniform
        const float cc = a2.x, ss = a2.y;
        const float br = src[j + 1].x, bi = src[j + 1].y;
        const float pr = cc * br, pi = cc * bi;
        const float nar = fmaf(cc, ar, -(ss * bi));
        const float nai = fmaf(cc, ai,   ss * br);
        const float nbr = fmaf(-ss, ai, pr);
        const float nbi = fmaf( ss, ar, pi);
        dst[j] = make_float2(nar, nai);
        ar = nbr; ai = nbi;
    }
    {   // last step j = i-1: partner row i is still identity
        const float2 a2 = ang[kbase + i - 1];
        const float cc = a2.x, ss = a2.y;
        const float br = (t == i) ? 1.0f : 0.0f;
        dst[i - 1] = make_float2(fmaf(cc, ar, 0.0f) * 1.0f - 0.0f,  0.0f);
        // recompute properly (bi = 0):
        dst[i - 1] = make_float2(cc * ar, fmaf(cc, ai, ss * br));
        dst[i]     = make_float2(fmaf(cc, br, -(ss * ai)),
                                  ss * ar);       // cc*bi = 0
    }
}

__global__ __launch_bounds__(64)
void build_u_kernel(const float* __restrict__ phases, int nph) {
    __shared__ float2 ang[NPH];      // 16128 B static

    const int t = threadIdx.x;       // column 0..63
    const int pmax = (nph > 0) ? (nph - 1) : 0;

    for (int k = t; k < NPH; k += 64) {
        const int kk = (k < pmax) ? k : pmax;
        float sv, cv;
        sincosf(phases[kk], &sv, &cv);
        ang[k] = make_float2(LOSS_AMP * cv, LOSS_AMP * sv);
    }
    __syncthreads();

    // thread-private ping-pong column buffers (local memory, exact no-alias)
    float2 La[SIZE], Lb[SIZE];
    La[0] = make_float2(t == 0 ? 1.0f : 0.0f, 0.0f);

    // layers 1..63: odd i -> La->Lb, even i -> Lb->La. 63 odd => final in Lb.
    for (int i = 1; i < SIZE; i += 2) {
        layer_col(i, (i * (i - 1)) >> 1, La, Lb, ang, t);
        if (i + 1 < SIZE)
            layer_col(i + 1, ((i + 1) * i) >> 1, Lb, La, ang, t);
    }

    // Thread t supplies W columns k' = t and t+64 for all 128 n':
    //   n'<64:  [ Ur | -Ui ] ; n'>=64: [ Ui | Ur ]
    #pragma unroll 8
    for (int n = 0; n < SIZE; ++n) {
        const float2 u = Lb[n];
        w_store(n,      t,       u.x);
        w_store(n,      t + 64, -u.y);
        w_store(n + 64, t,       u.y);
        w_store(n + 64, t + 64,  u.x);
    }
}

// ----------------------------- GEMM kernel (R16, unchanged) ---------------
__global__ __launch_bounds__(256, 2)
void photonic_mma_kernel(const float* __restrict__ xr_g,
                         const float* __restrict__ xi_g,
                         float* __restrict__ out,
                         long long xsz, long long out_elems, int B) {
    extern __shared__ char smem[];
    unsigned* sxA = (unsigned*)smem;          // packed A: 64 KB

    const int tid  = threadIdx.x;
    const int lane = tid & 31;
    const int warp = tid >> 5;
    const int g = lane >> 2;
    const int t = lane & 3;
    const int warpM = warp >> 2;              // 0..1
    const int warpN = warp & 3;               // 0..3

    const long long b0 = (long long)blockIdx.x * 128;
    if (b0 >= B) return;
    const long long base = b0 * SIZE;
    const long long xmax = xsz - 1;

    // ---- stage X = [xr | xi], tf32-rounded, in A-fragment order ----
    #pragma unroll 8
    for (int p = tid; p < 128 * 64; p += 256) {
        const int bb = p >> 6, k = p & 63;
        long long gi = base + p;
        if (gi > xmax) gi = xmax;
        const float vr = xr_g[gi];
        const float vi = xi_g[gi];
        unsigned r_, i_;
        asm("cvt.rna.tf32.f32 %0, %1;" : "=r"(r_) : "f"(vr));
        asm("cvt.rna.tf32.f32 %0, %1;" : "=r"(i_) : "f"(vi));
        const int m16t = bb >> 4, gg = bb & 7, half = (bb >> 3) & 1;
        const int tt = k & 3, q = (k >> 2) & 1;
        const int bse = (m16t * 16) * 128 + (gg * 4 + tt) * 4 + half + 2 * q;
        sxA[bse + ((k >> 3)) * 128]     = r_;
        sxA[bse + ((k >> 3) + 8) * 128] = i_;
    }
    __syncthreads();

    float c[4][4][4];
    #pragma unroll
    for (int mt = 0; mt < 4; ++mt)
        #pragma unroll
        for (int nt = 0; nt < 4; ++nt)
            #pragma unroll
            for (int q2 = 0; q2 < 4; ++q2) c[mt][nt][q2] = 0.0f;

    const unsigned* sA = &sxA[((warpM * 4) * 16) * 128 + lane * 4];
    const unsigned* wp0 = &g_Wfrag[(((warpN * 2    ) * 16) * 32 + lane) << 1];
    const unsigned* wp1 = &g_Wfrag[(((warpN * 2 + 1) * 16) * 32 + lane) << 1];
    const unsigned* wp2 = &g_Wfrag[(((warpN * 2 + 8) * 16) * 32 + lane) << 1];
    const unsigned* wp3 = &g_Wfrag[(((warpN * 2 + 9) * 16) * 32 + lane) << 1];

    #pragma unroll
    for (int ks = 0; ks < 16; ++ks) {
        uint4 a[4];
        #pragma unroll
        for (int mt = 0; mt < 4; ++mt)
            a[mt] = *(const uint4*)&sA[(mt * 16 + ks) * 128];
        uint2 bf[4];
        bf[0] = __ldg((const uint2*)&wp0[ks * 64]);
        bf[1] = __ldg((const uint2*)&wp1[ks * 64]);
        bf[2] = __ldg((const uint2*)&wp2[ks * 64]);
        bf[3] = __ldg((const uint2*)&wp3[ks * 64]);
        #pragma unroll
        for (int mt = 0; mt < 4; ++mt)
            #pragma unroll
            for (int nt = 0; nt < 4; ++nt)
                asm volatile(
                    "mma.sync.aligned.m16n8k8.row.col.f32.tf32.tf32.f32 "
                    "{%0,%1,%2,%3}, {%4,%5,%6,%7}, {%8,%9}, {%0,%1,%2,%3};"
                    : "+f"(c[mt][nt][0]), "+f"(c[mt][nt][1]),
                      "+f"(c[mt][nt][2]), "+f"(c[mt][nt][3])
                    : "r"(a[mt].x), "r"(a[mt].y), "r"(a[mt].z), "r"(a[mt].w),
                      "r"(bf[nt].x), "r"(bf[nt].y));
    }

    #pragma unroll
    for (int mt = 0; mt < 4; ++mt) {
        const int row0 = warpM * 64 + mt * 16 + g;
        #pragma unroll
        for (int ci = 0; ci < 2; ++ci) {
            const int n = (warpN * 2 + ci) * 8 + 2 * t;
            #pragma unroll
            for (int h = 0; h < 2; ++h) {
                const int row = row0 + 8 * h;
                const float re0 = c[mt][ci][2 * h];
                const float re1 = c[mt][ci][2 * h + 1];
                const float im0 = c[mt][ci + 2][2 * h];
                const float im1 = c[mt][ci + 2][2 * h + 1];
                const float ph0 = KERR * fmaf(re0, re0, im0 * im0);
                const float ph1 = KERR * fmaf(re1, re1, im1 * im1);
                const long long o = base + (long long)row * 64 + n;
                if (o + 2 <= out_elems)
                    *(float2*)&out[o] = make_float2(fmaf(-im0, ph0, re0),
                                                    fmaf(-im1, ph1, re1));
            }
        }
    }
}

// ------------------------------- launch ------------------------------------
extern "C" void kernel_launch(void* const* d_in, const int* in_sizes, int n_in,
                              void* d_out, int out_size) {
    if (n_in < 3) return;

    int ph_idx = 0;
    for (int i = 1; i < 3; ++i)
        if (in_sizes[i] < in_sizes[ph_idx]) ph_idx = i;

    const float* xr = nullptr;
    const float* xi = nullptr;
    long long xsz = 0;
    for (int i = 0; i < 3; ++i) {
        if (i == ph_idx) continue;
        if (!xr) { xr = (const float*)d_in[i]; xsz = in_sizes[i]; }
        else     { xi = (const float*)d_in[i]; }
    }
    const float* phases = (const float*)d_in[ph_idx];
    const int nph = in_sizes[ph_idx];

    const int B = (int)(xsz / SIZE);
    const int nblocks = (B + 127) / 128;

    cudaFuncSetAttribute(photonic_mma_kernel,
                         cudaFuncAttributeMaxDynamicSharedMemorySize,
                         65536);

    build_u_kernel<<<1, 64>>>(phases, nph);
    photonic_mma_kernel<<<nblocks, 256, 65536>>>(
        xr, xi, (float*)d_out, xsz, (long long)out_size, B);
}